// round 6
// baseline (speedup 1.0000x reference)
#include <cuda_runtime.h>
#include <cuda_bf16.h>

// ---------------------------------------------------------------------------
// GCN 3-layer forward on GB300.
//   prep: dtype-sniff -> hist(dst) -> scan(+dinv) -> place packed (src,coef)
//   layer: register-blocked FFMA2 GEMM -> warp-per-node float4 gather (1 LDG/edge)
// ---------------------------------------------------------------------------

#define N_NODES 100000
#define N_EDGES 1600000
#define SCAN_BS 1024
#define SCAN_NB ((N_NODES + SCAN_BS - 1) / SCAN_BS)

__device__ __align__(16) float  g_h[N_NODES * 64];
__device__ __align__(16) float  g_aggA[N_NODES * 64];
__device__ __align__(16) float  g_aggB[N_NODES * 64];
__device__ float  g_dinv[N_NODES];
__device__ int2   g_sd[N_EDGES];      // packed (src,dst) from input
__device__ int    g_cnt[N_NODES];
__device__ int    g_rowptr[N_NODES + 1];
__device__ int    g_cursor[N_NODES];
__device__ int    g_bsum[SCAN_NB];
__device__ __align__(8) float2 g_epack[N_EDGES];  // CSR: {src bits, coef}
__device__ int    g_is64;

#define FMA2(d, a, b) \
    asm("fma.rn.f32x2 %0, %1, %2, %0;" : "+l"(d) : "l"(a), "l"(b))
#define PACKXX(d, x) \
    asm("mov.b64 %0, {%1, %1};" : "=l"(d) : "f"(x))

// ---------------------------------------------------------------------------
// Prep
// ---------------------------------------------------------------------------
__global__ void detect_zero_kernel(const int* __restrict__ w, int n) {
    int i = blockIdx.x * blockDim.x + threadIdx.x;
    if (i < n) g_cnt[i] = 0;
    if (blockIdx.x == 0) {
        // odd int32 words: int64 -> always 0 (high words); int32 -> src ids.
        __shared__ int nonzero;
        if (threadIdx.x == 0) nonzero = 0;
        __syncthreads();
        if (w[2 * threadIdx.x + 1] != 0) atomicOr(&nonzero, 1);
        __syncthreads();
        if (threadIdx.x == 0) g_is64 = (nonzero == 0) ? 1 : 0;
    }
}

__global__ void hist_kernel(const void* __restrict__ ei, int ne) {
    int e = blockIdx.x * blockDim.x + threadIdx.x;
    if (e >= ne) return;
    int s, d;
    if (g_is64) {
        const long long* p = (const long long*)ei;
        s = (int)p[e];
        d = (int)p[ne + e];
    } else {
        const int* p = (const int*)ei;
        s = p[e];
        d = p[ne + e];
    }
    g_sd[e] = make_int2(s, d);
    atomicAdd(&g_cnt[d], 1);
}

__global__ void scan1_kernel(int n) {   // block-local exclusive scan + dinv
    __shared__ int sm[SCAN_BS];
    int t = threadIdx.x;
    int i = blockIdx.x * SCAN_BS + t;
    int v = (i < n) ? g_cnt[i] : 0;
    sm[t] = v;
    __syncthreads();
    for (int off = 1; off < SCAN_BS; off <<= 1) {
        int u = (t >= off) ? sm[t - off] : 0;
        __syncthreads();
        sm[t] += u;
        __syncthreads();
    }
    if (i < n) {
        g_rowptr[i] = sm[t] - v;
        g_dinv[i]   = rsqrtf((float)v + 1.0f);
    }
    if (t == SCAN_BS - 1) g_bsum[blockIdx.x] = sm[t];
}

// scan3: add cross-block prefix (computed locally by one warp) + init cursor.
// Each 256-thread block spans exactly one scan1 block (1024 % 256 == 0).
__global__ void scan3_kernel(int n, int ne) {
    __shared__ int s_pref;
    const int t = threadIdx.x;
    const int b = (blockIdx.x * 256) / SCAN_BS;   // enclosing scan1 block
    if (t < 32) {
        int v = 0;
        for (int j = t; j < b; j += 32) v += g_bsum[j];
#pragma unroll
        for (int o = 16; o; o >>= 1) v += __shfl_down_sync(0xffffffffu, v, o);
        if (t == 0) s_pref = v;
    }
    __syncthreads();
    int i = blockIdx.x * 256 + t;
    if (i < n) {
        int r = g_rowptr[i] + s_pref;
        g_rowptr[i] = r;
        g_cursor[i] = r;
    }
    if (i == 0) g_rowptr[n] = ne;
}

__global__ void place_kernel(int ne) {
    int e = blockIdx.x * blockDim.x + threadIdx.x;
    if (e >= ne) return;
    int2 sd = g_sd[e];
    int pos = atomicAdd(&g_cursor[sd.y], 1);
    g_epack[pos] = make_float2(__int_as_float(sd.x), g_dinv[sd.x] * g_dinv[sd.y]);
}

// ---------------------------------------------------------------------------
// Register-blocked GEMM, DOUT=64: h = relu?(in) @ W.
// 128 threads: cg=tid&7 (cols cg*4..+3 and 32+cg*4..+3), tr=tid>>3
// (rows tr+16j, j=0..7). 32 f32x2 accumulators (8 rows x 4 col-pairs).
// XS = DIN+4 keeps float4 row staging 16B-aligned and banks conflict-free.
// ---------------------------------------------------------------------------
template <int DIN, int TILE_R, bool RELU_IN>
__global__ void __launch_bounds__(128) gemm64_kernel(const float* __restrict__ in,
                                                     const float* __restrict__ W,
                                                     float* __restrict__ h_out,
                                                     int n)
{
    constexpr int DOUT = 64;
    constexpr int XS = DIN + 4;     // 16B-aligned row stride (132 / 68 floats)
    extern __shared__ float sm[];
    float* sW = sm;                 // DIN*DOUT
    float* sX = sm + DIN * DOUT;    // TILE_R*XS

    const int tid  = threadIdx.x;
    const int row0 = blockIdx.x * TILE_R;

    const float4* Wv  = (const float4*)W;
    float4*       sWv = (float4*)sW;
    for (int i = tid; i < DIN * DOUT / 4; i += 128) sWv[i] = Wv[i];

    for (int i = tid; i < TILE_R * DIN / 4; i += 128) {
        int r  = i / (DIN / 4);
        int kq = i - r * (DIN / 4);
        int gr = row0 + r;
        float4 v = make_float4(0.f, 0.f, 0.f, 0.f);
        if (gr < n) v = ((const float4*)in)[gr * (DIN / 4) + kq];
        if (RELU_IN) {
            v.x = fmaxf(v.x, 0.f); v.y = fmaxf(v.y, 0.f);
            v.z = fmaxf(v.z, 0.f); v.w = fmaxf(v.w, 0.f);
        }
        *(float4*)&sX[r * XS + kq * 4] = v;
    }
    __syncthreads();

    const int cg = tid & 7;
    const int tr = tid >> 3;

    unsigned long long acc[8][4];
#pragma unroll
    for (int j = 0; j < 8; j++)
#pragma unroll
        for (int p = 0; p < 4; p++) acc[j][p] = 0ULL;

    const float* xbase = sX + tr * XS;
    const ulonglong2* wv = (const ulonglong2*)sW;

#pragma unroll 4
    for (int k = 0; k < DIN; k++) {
        // two conflict-free LDS.128: 8 lanes x 16B contiguous per instruction
        ulonglong2 wA = wv[k * (DOUT / 4) + cg];       // cols cg*4..cg*4+3
        ulonglong2 wB = wv[k * (DOUT / 4) + 8 + cg];   // cols 32+cg*4..+3
#pragma unroll
        for (int j = 0; j < 8; j++) {
            float xv = xbase[j * 16 * XS + k];
            unsigned long long xx;
            PACKXX(xx, xv);
            FMA2(acc[j][0], xx, wA.x);
            FMA2(acc[j][1], xx, wA.y);
            FMA2(acc[j][2], xx, wB.x);
            FMA2(acc[j][3], xx, wB.y);
        }
    }

#pragma unroll
    for (int j = 0; j < 8; j++) {
        int r = row0 + tr + 16 * j;
        if (r < n) {
            ulonglong2* o = (ulonglong2*)&h_out[r * DOUT + cg * 4];
            o[0] = make_ulonglong2(acc[j][0], acc[j][1]);          // cols cg*4..
            o[8] = make_ulonglong2(acc[j][2], acc[j][3]);          // cols 32+cg*4..
        }
    }
}

// ---------------------------------------------------------------------------
// GEMM for DOUT=40 (layer 3) — smem-walk version (small share of runtime).
// ---------------------------------------------------------------------------
template <int DIN, int DOUT, int CGROUPS, int TILE_R, bool RELU_IN>
__global__ void gemm_kernel(const float* __restrict__ in,
                            const float* __restrict__ W,
                            float* __restrict__ h_out,
                            int n)
{
    constexpr int CP = DOUT / CGROUPS;
    constexpr int XS = DIN + 1;
    extern __shared__ float sm[];
    float* sW = sm;
    float* sX = sm + DIN * DOUT;

    const int tid  = threadIdx.x;
    const int nthr = blockDim.x;
    const int row0 = blockIdx.x * TILE_R;

    for (int i = tid; i < DIN * DOUT; i += nthr) sW[i] = W[i];
    for (int i = tid; i < TILE_R * DIN; i += nthr) {
        int r = i / DIN;
        int k = i - r * DIN;
        int gr = row0 + r;
        float v = 0.0f;
        if (gr < n) v = in[gr * DIN + k];
        if (RELU_IN) v = fmaxf(v, 0.0f);
        sX[r * XS + k] = v;
    }
    __syncthreads();

    const int rl = tid / CGROUPS;
    const int cg = tid - rl * CGROUPS;
    const int c0 = cg * CP;

    float acc[CP];
#pragma unroll
    for (int j = 0; j < CP; j++) acc[j] = 0.0f;

    const float* xrow = &sX[rl * XS];
#pragma unroll 4
    for (int k = 0; k < DIN; k++) {
        float xv = xrow[k];
        const float4* wrow = reinterpret_cast<const float4*>(&sW[k * DOUT + c0]);
#pragma unroll
        for (int j4 = 0; j4 < CP / 4; j4++) {
            float4 w = wrow[j4];
            acc[j4 * 4 + 0] = fmaf(xv, w.x, acc[j4 * 4 + 0]);
            acc[j4 * 4 + 1] = fmaf(xv, w.y, acc[j4 * 4 + 1]);
            acc[j4 * 4 + 2] = fmaf(xv, w.z, acc[j4 * 4 + 2]);
            acc[j4 * 4 + 3] = fmaf(xv, w.w, acc[j4 * 4 + 3]);
        }
    }

    const int r = row0 + rl;
    if (r < n) {
#pragma unroll
        for (int j4 = 0; j4 < CP / 4; j4++) {
            float4 hv = make_float4(acc[j4 * 4 + 0], acc[j4 * 4 + 1],
                                    acc[j4 * 4 + 2], acc[j4 * 4 + 3]);
            *reinterpret_cast<float4*>(&h_out[r * DOUT + c0 + j4 * 4]) = hv;
        }
    }
}

// ---------------------------------------------------------------------------
// Aggregation DOUT=64: warp per node, half-warp per edge, 4 edges in flight.
// ---------------------------------------------------------------------------
__global__ void aggregate64_kernel(const float* __restrict__ h,
                                   const float* __restrict__ bias,
                                   float* __restrict__ out,
                                   int n)
{
    int w = (blockIdx.x * blockDim.x + threadIdx.x) >> 5;
    if (w >= n) return;
    int lane = threadIdx.x & 31;
    int half = lane >> 4;
    int sub  = lane & 15;

    int c0 = g_rowptr[w];
    int c1 = g_rowptr[w + 1];

    const float4* hp4 = (const float4*)h;   // 16 float4 per row
    float4 acc = make_float4(0.f, 0.f, 0.f, 0.f);

    int i = c0;
    for (; i + 4 <= c1; i += 4) {           // 4 edges in flight (2 per half)
        float2 p0 = g_epack[i + half];
        float2 p1 = g_epack[i + 2 + half];
        int s0 = __float_as_int(p0.x);
        int s1 = __float_as_int(p1.x);
        float4 v0 = hp4[s0 * 16 + sub];
        float4 v1 = hp4[s1 * 16 + sub];
        acc.x = fmaf(v0.x, p0.y, acc.x);
        acc.y = fmaf(v0.y, p0.y, acc.y);
        acc.z = fmaf(v0.z, p0.y, acc.z);
        acc.w = fmaf(v0.w, p0.y, acc.w);
        acc.x = fmaf(v1.x, p1.y, acc.x);
        acc.y = fmaf(v1.y, p1.y, acc.y);
        acc.z = fmaf(v1.z, p1.y, acc.z);
        acc.w = fmaf(v1.w, p1.y, acc.w);
    }
    for (; i < c1; i += 2) {                // 0..3 remaining edges
        int e = i + half;
        if (e < c1) {
            float2 pk = g_epack[e];
            int   s = __float_as_int(pk.x);
            float c = pk.y;
            float4 v = hp4[s * 16 + sub];
            acc.x = fmaf(v.x, c, acc.x);
            acc.y = fmaf(v.y, c, acc.y);
            acc.z = fmaf(v.z, c, acc.z);
            acc.w = fmaf(v.w, c, acc.w);
        }
    }
    // combine the two half-warp partial sums
    acc.x += __shfl_xor_sync(0xffffffffu, acc.x, 16);
    acc.y += __shfl_xor_sync(0xffffffffu, acc.y, 16);
    acc.z += __shfl_xor_sync(0xffffffffu, acc.z, 16);
    acc.w += __shfl_xor_sync(0xffffffffu, acc.w, 16);

    float di  = g_dinv[w];
    float di2 = di * di;
    float4 hs = hp4[w * 16 + sub];
    float4 bv = ((const float4*)bias)[sub];
    float4 r;
    r.x = fmaf(hs.x, di2, acc.x) + bv.x;
    r.y = fmaf(hs.y, di2, acc.y) + bv.y;
    r.z = fmaf(hs.z, di2, acc.z) + bv.z;
    r.w = fmaf(hs.w, di2, acc.w) + bv.w;
    if (half == 0) ((float4*)out)[w * 16 + sub] = r;
}

// ---------------------------------------------------------------------------
// Aggregation DOUT=40: warp per node, half-warp per edge (lanes sub<10 do
// float4 loads -> 40 cols), 2 edges in flight, shfl-combine halves.
// ---------------------------------------------------------------------------
__global__ void aggregate40_kernel(const float* __restrict__ h,
                                   const float* __restrict__ bias,
                                   float* __restrict__ out,
                                   int n)
{
    int w = (blockIdx.x * blockDim.x + threadIdx.x) >> 5;
    if (w >= n) return;
    int lane = threadIdx.x & 31;
    int half = lane >> 4;
    int sub  = lane & 15;
    bool act = (sub < 10);                  // 10 float4 = 40 floats

    int c0 = g_rowptr[w];
    int c1 = g_rowptr[w + 1];

    float4 acc = make_float4(0.f, 0.f, 0.f, 0.f);
    for (int i = c0; i < c1; i += 2) {
        int e = i + half;
        if (e < c1) {
            float2 pk = g_epack[e];
            int   s = __float_as_int(pk.x);
            float c = pk.y;
            if (act) {
                float4 v = *(const float4*)&h[s * 40 + sub * 4];
                acc.x = fmaf(v.x, c, acc.x);
                acc.y = fmaf(v.y, c, acc.y);
                acc.z = fmaf(v.z, c, acc.z);
                acc.w = fmaf(v.w, c, acc.w);
            }
        }
    }
    acc.x += __shfl_xor_sync(0xffffffffu, acc.x, 16);
    acc.y += __shfl_xor_sync(0xffffffffu, acc.y, 16);
    acc.z += __shfl_xor_sync(0xffffffffu, acc.z, 16);
    acc.w += __shfl_xor_sync(0xffffffffu, acc.w, 16);

    if (half == 0 && act) {
        float di  = g_dinv[w];
        float di2 = di * di;
        float4 hs = *(const float4*)&h[w * 40 + sub * 4];
        float4 bv = *(const float4*)&bias[sub * 4];
        float4 r;
        r.x = fmaf(hs.x, di2, acc.x) + bv.x;
        r.y = fmaf(hs.y, di2, acc.y) + bv.y;
        r.z = fmaf(hs.z, di2, acc.z) + bv.z;
        r.w = fmaf(hs.w, di2, acc.w) + bv.w;
        *(float4*)&out[w * 40 + sub * 4] = r;
    }
}

// ---------------------------------------------------------------------------
// Launch
// ---------------------------------------------------------------------------
extern "C" void kernel_launch(void* const* d_in, const int* in_sizes, int n_in,
                              void* d_out, int out_size)
{
    const float* x  = (const float*)d_in[0];
    const void*  ei = d_in[1];
    const float* W1 = (const float*)d_in[2];
    const float* b1 = (const float*)d_in[3];
    const float* W2 = (const float*)d_in[4];
    const float* b2 = (const float*)d_in[5];
    const float* W3 = (const float*)d_in[6];
    const float* b3 = (const float*)d_in[7];
    float* out = (float*)d_out;

    const int N = in_sizes[0] / 128;   // 100000
    const int E = in_sizes[1] / 2;     // 1600000

    float *h, *aggA, *aggB;
    cudaGetSymbolAddress((void**)&h,    g_h);
    cudaGetSymbolAddress((void**)&aggA, g_aggA);
    cudaGetSymbolAddress((void**)&aggB, g_aggB);

    // --- prep ---
    detect_zero_kernel<<<(N + 255) / 256, 256>>>((const int*)ei, N);
    hist_kernel<<<(E + 255) / 256, 256>>>(ei, E);
    const int nb = (N + SCAN_BS - 1) / SCAN_BS;
    scan1_kernel<<<nb, SCAN_BS>>>(N);
    scan3_kernel<<<(N + 255) / 256, 256>>>(N, E);
    place_kernel<<<(E + 255) / 256, 256>>>(E);

    constexpr int TRB = 128;                       // big-GEMM row tile
    const int g2_grid  = (N + TRB - 1) / TRB;
    const int agg_grid = (N * 32 + 255) / 256;

    // --- layer 1: 128 -> 64 ---
    const int smem1 = (128 * 64 + TRB * (128 + 4)) * (int)sizeof(float);  // ~100.4KB
    cudaFuncSetAttribute(gemm64_kernel<128, TRB, false>,
                         cudaFuncAttributeMaxDynamicSharedMemorySize, smem1);
    gemm64_kernel<128, TRB, false><<<g2_grid, 128, smem1>>>(x, W1, h, N);
    aggregate64_kernel<<<agg_grid, 256>>>(h, b1, aggA, N);

    // --- layer 2: 64 -> 64 ---
    const int smem2 = (64 * 64 + TRB * (64 + 4)) * (int)sizeof(float);    // ~51.2KB
    cudaFuncSetAttribute(gemm64_kernel<64, TRB, true>,
                         cudaFuncAttributeMaxDynamicSharedMemorySize, smem2);
    gemm64_kernel<64, TRB, true><<<g2_grid, 128, smem2>>>(aggA, W2, h, N);
    aggregate64_kernel<<<agg_grid, 256>>>(h, b2, aggB, N);

    // --- layer 3: 64 -> 40 ---
    constexpr int TR3 = 64;
    const int g3_grid = (N + TR3 - 1) / TR3;
    const int smem3 = (64 * 40 + TR3 * (64 + 1)) * (int)sizeof(float);
    gemm_kernel<64, 40, 5, TR3, true><<<g3_grid, TR3 * 5, smem3>>>(aggB, W3, h, N);
    aggregate40_kernel<<<agg_grid, 256>>>(h, b3, out, N);
}

// round 7
// speedup vs baseline: 1.0952x; 1.0952x over previous
#include <cuda_runtime.h>
#include <cuda_bf16.h>

// ---------------------------------------------------------------------------
// GCN 3-layer forward on GB300.
//   prep: dtype-sniff -> hist(dst) -> scan(+dinv) -> place packed (src,coef)
//   layer: register-blocked FFMA2 GEMM -> warp-per-node float4 gather (1 LDG/edge)
// R7: aggregation kernels reverted to the measured-313.4us forms; fused scan
//     prefix (no scan2) kept.
// ---------------------------------------------------------------------------

#define N_NODES 100000
#define N_EDGES 1600000
#define SCAN_BS 1024
#define SCAN_NB ((N_NODES + SCAN_BS - 1) / SCAN_BS)

__device__ __align__(16) float  g_h[N_NODES * 64];
__device__ __align__(16) float  g_aggA[N_NODES * 64];
__device__ __align__(16) float  g_aggB[N_NODES * 64];
__device__ float  g_dinv[N_NODES];
__device__ int2   g_sd[N_EDGES];      // packed (src,dst) from input
__device__ int    g_cnt[N_NODES];
__device__ int    g_rowptr[N_NODES + 1];
__device__ int    g_cursor[N_NODES];
__device__ int    g_bsum[SCAN_NB];
__device__ __align__(8) float2 g_epack[N_EDGES];  // CSR: {src bits, coef}
__device__ int    g_is64;

#define FMA2(d, a, b) \
    asm("fma.rn.f32x2 %0, %1, %2, %0;" : "+l"(d) : "l"(a), "l"(b))
#define PACKXX(d, x) \
    asm("mov.b64 %0, {%1, %1};" : "=l"(d) : "f"(x))

// ---------------------------------------------------------------------------
// Prep
// ---------------------------------------------------------------------------
__global__ void detect_zero_kernel(const int* __restrict__ w, int n) {
    int i = blockIdx.x * blockDim.x + threadIdx.x;
    if (i < n) g_cnt[i] = 0;
    if (blockIdx.x == 0) {
        // odd int32 words: int64 -> always 0 (high words); int32 -> src ids.
        __shared__ int nonzero;
        if (threadIdx.x == 0) nonzero = 0;
        __syncthreads();
        if (w[2 * threadIdx.x + 1] != 0) atomicOr(&nonzero, 1);
        __syncthreads();
        if (threadIdx.x == 0) g_is64 = (nonzero == 0) ? 1 : 0;
    }
}

__global__ void hist_kernel(const void* __restrict__ ei, int ne) {
    int e = blockIdx.x * blockDim.x + threadIdx.x;
    if (e >= ne) return;
    int s, d;
    if (g_is64) {
        const long long* p = (const long long*)ei;
        s = (int)p[e];
        d = (int)p[ne + e];
    } else {
        const int* p = (const int*)ei;
        s = p[e];
        d = p[ne + e];
    }
    g_sd[e] = make_int2(s, d);
    atomicAdd(&g_cnt[d], 1);
}

__global__ void scan1_kernel(int n) {   // block-local exclusive scan + dinv
    __shared__ int sm[SCAN_BS];
    int t = threadIdx.x;
    int i = blockIdx.x * SCAN_BS + t;
    int v = (i < n) ? g_cnt[i] : 0;
    sm[t] = v;
    __syncthreads();
    for (int off = 1; off < SCAN_BS; off <<= 1) {
        int u = (t >= off) ? sm[t - off] : 0;
        __syncthreads();
        sm[t] += u;
        __syncthreads();
    }
    if (i < n) {
        g_rowptr[i] = sm[t] - v;
        g_dinv[i]   = rsqrtf((float)v + 1.0f);
    }
    if (t == SCAN_BS - 1) g_bsum[blockIdx.x] = sm[t];
}

// scan3: add cross-block prefix (computed locally by one warp) + init cursor.
// Each 256-thread block spans exactly one scan1 block (1024 % 256 == 0).
__global__ void scan3_kernel(int n, int ne) {
    __shared__ int s_pref;
    const int t = threadIdx.x;
    const int b = (blockIdx.x * 256) / SCAN_BS;   // enclosing scan1 block
    if (t < 32) {
        int v = 0;
        for (int j = t; j < b; j += 32) v += g_bsum[j];
#pragma unroll
        for (int o = 16; o; o >>= 1) v += __shfl_down_sync(0xffffffffu, v, o);
        if (t == 0) s_pref = v;
    }
    __syncthreads();
    int i = blockIdx.x * 256 + t;
    if (i < n) {
        int r = g_rowptr[i] + s_pref;
        g_rowptr[i] = r;
        g_cursor[i] = r;
    }
    if (i == 0) g_rowptr[n] = ne;
}

__global__ void place_kernel(int ne) {
    int e = blockIdx.x * blockDim.x + threadIdx.x;
    if (e >= ne) return;
    int2 sd = g_sd[e];
    int pos = atomicAdd(&g_cursor[sd.y], 1);
    g_epack[pos] = make_float2(__int_as_float(sd.x), g_dinv[sd.x] * g_dinv[sd.y]);
}

// ---------------------------------------------------------------------------
// Register-blocked GEMM, DOUT=64: h = relu?(in) @ W.
// 128 threads: cg=tid&7 (cols cg*4..+3 and 32+cg*4..+3), tr=tid>>3
// (rows tr+16j, j=0..7). 32 f32x2 accumulators (8 rows x 4 col-pairs).
// XS = DIN+4 keeps float4 row staging 16B-aligned and banks conflict-free.
// ---------------------------------------------------------------------------
template <int DIN, int TILE_R, bool RELU_IN>
__global__ void __launch_bounds__(128) gemm64_kernel(const float* __restrict__ in,
                                                     const float* __restrict__ W,
                                                     float* __restrict__ h_out,
                                                     int n)
{
    constexpr int DOUT = 64;
    constexpr int XS = DIN + 4;     // 16B-aligned row stride (132 / 68 floats)
    extern __shared__ float sm[];
    float* sW = sm;                 // DIN*DOUT
    float* sX = sm + DIN * DOUT;    // TILE_R*XS

    const int tid  = threadIdx.x;
    const int row0 = blockIdx.x * TILE_R;

    const float4* Wv  = (const float4*)W;
    float4*       sWv = (float4*)sW;
    for (int i = tid; i < DIN * DOUT / 4; i += 128) sWv[i] = Wv[i];

    for (int i = tid; i < TILE_R * DIN / 4; i += 128) {
        int r  = i / (DIN / 4);
        int kq = i - r * (DIN / 4);
        int gr = row0 + r;
        float4 v = make_float4(0.f, 0.f, 0.f, 0.f);
        if (gr < n) v = ((const float4*)in)[gr * (DIN / 4) + kq];
        if (RELU_IN) {
            v.x = fmaxf(v.x, 0.f); v.y = fmaxf(v.y, 0.f);
            v.z = fmaxf(v.z, 0.f); v.w = fmaxf(v.w, 0.f);
        }
        *(float4*)&sX[r * XS + kq * 4] = v;
    }
    __syncthreads();

    const int cg = tid & 7;
    const int tr = tid >> 3;

    unsigned long long acc[8][4];
#pragma unroll
    for (int j = 0; j < 8; j++)
#pragma unroll
        for (int p = 0; p < 4; p++) acc[j][p] = 0ULL;

    const float* xbase = sX + tr * XS;
    const ulonglong2* wv = (const ulonglong2*)sW;

#pragma unroll 4
    for (int k = 0; k < DIN; k++) {
        // two conflict-free LDS.128: 8 lanes x 16B contiguous per instruction
        ulonglong2 wA = wv[k * (DOUT / 4) + cg];       // cols cg*4..cg*4+3
        ulonglong2 wB = wv[k * (DOUT / 4) + 8 + cg];   // cols 32+cg*4..+3
#pragma unroll
        for (int j = 0; j < 8; j++) {
            float xv = xbase[j * 16 * XS + k];
            unsigned long long xx;
            PACKXX(xx, xv);
            FMA2(acc[j][0], xx, wA.x);
            FMA2(acc[j][1], xx, wA.y);
            FMA2(acc[j][2], xx, wB.x);
            FMA2(acc[j][3], xx, wB.y);
        }
    }

#pragma unroll
    for (int j = 0; j < 8; j++) {
        int r = row0 + tr + 16 * j;
        if (r < n) {
            ulonglong2* o = (ulonglong2*)&h_out[r * DOUT + cg * 4];
            o[0] = make_ulonglong2(acc[j][0], acc[j][1]);          // cols cg*4..
            o[8] = make_ulonglong2(acc[j][2], acc[j][3]);          // cols 32+cg*4..
        }
    }
}

// ---------------------------------------------------------------------------
// GEMM for DOUT=40 (layer 3) — smem-walk version (small share of runtime).
// ---------------------------------------------------------------------------
template <int DIN, int DOUT, int CGROUPS, int TILE_R, bool RELU_IN>
__global__ void gemm_kernel(const float* __restrict__ in,
                            const float* __restrict__ W,
                            float* __restrict__ h_out,
                            int n)
{
    constexpr int CP = DOUT / CGROUPS;
    constexpr int XS = DIN + 1;
    extern __shared__ float sm[];
    float* sW = sm;
    float* sX = sm + DIN * DOUT;

    const int tid  = threadIdx.x;
    const int nthr = blockDim.x;
    const int row0 = blockIdx.x * TILE_R;

    for (int i = tid; i < DIN * DOUT; i += nthr) sW[i] = W[i];
    for (int i = tid; i < TILE_R * DIN; i += nthr) {
        int r = i / DIN;
        int k = i - r * DIN;
        int gr = row0 + r;
        float v = 0.0f;
        if (gr < n) v = in[gr * DIN + k];
        if (RELU_IN) v = fmaxf(v, 0.0f);
        sX[r * XS + k] = v;
    }
    __syncthreads();

    const int rl = tid / CGROUPS;
    const int cg = tid - rl * CGROUPS;
    const int c0 = cg * CP;

    float acc[CP];
#pragma unroll
    for (int j = 0; j < CP; j++) acc[j] = 0.0f;

    const float* xrow = &sX[rl * XS];
#pragma unroll 4
    for (int k = 0; k < DIN; k++) {
        float xv = xrow[k];
        const float4* wrow = reinterpret_cast<const float4*>(&sW[k * DOUT + c0]);
#pragma unroll
        for (int j4 = 0; j4 < CP / 4; j4++) {
            float4 w = wrow[j4];
            acc[j4 * 4 + 0] = fmaf(xv, w.x, acc[j4 * 4 + 0]);
            acc[j4 * 4 + 1] = fmaf(xv, w.y, acc[j4 * 4 + 1]);
            acc[j4 * 4 + 2] = fmaf(xv, w.z, acc[j4 * 4 + 2]);
            acc[j4 * 4 + 3] = fmaf(xv, w.w, acc[j4 * 4 + 3]);
        }
    }

    const int r = row0 + rl;
    if (r < n) {
#pragma unroll
        for (int j4 = 0; j4 < CP / 4; j4++) {
            float4 hv = make_float4(acc[j4 * 4 + 0], acc[j4 * 4 + 1],
                                    acc[j4 * 4 + 2], acc[j4 * 4 + 3]);
            *reinterpret_cast<float4*>(&h_out[r * DOUT + c0 + j4 * 4]) = hv;
        }
    }
}

// ---------------------------------------------------------------------------
// Aggregation DOUT=64: warp per node, 2 edges/iter (half-warps), float4 lanes.
// (measured-best form)
// ---------------------------------------------------------------------------
__global__ void aggregate64_kernel(const float* __restrict__ h,
                                   const float* __restrict__ bias,
                                   float* __restrict__ out,
                                   int n)
{
    int w = (blockIdx.x * blockDim.x + threadIdx.x) >> 5;
    if (w >= n) return;
    int lane = threadIdx.x & 31;
    int half = lane >> 4;
    int sub  = lane & 15;

    int c0 = g_rowptr[w];
    int c1 = g_rowptr[w + 1];

    const float4* hp4 = (const float4*)h;   // 16 float4 per row
    float4 acc = make_float4(0.f, 0.f, 0.f, 0.f);

#pragma unroll 2
    for (int i = c0; i < c1; i += 2) {
        int e = i + half;
        if (e < c1) {
            float2 pk = g_epack[e];
            int   s = __float_as_int(pk.x);
            float c = pk.y;
            float4 v = hp4[s * 16 + sub];
            acc.x = fmaf(v.x, c, acc.x);
            acc.y = fmaf(v.y, c, acc.y);
            acc.z = fmaf(v.z, c, acc.z);
            acc.w = fmaf(v.w, c, acc.w);
        }
    }
    // combine the two half-warp partial sums
    acc.x += __shfl_xor_sync(0xffffffffu, acc.x, 16);
    acc.y += __shfl_xor_sync(0xffffffffu, acc.y, 16);
    acc.z += __shfl_xor_sync(0xffffffffu, acc.z, 16);
    acc.w += __shfl_xor_sync(0xffffffffu, acc.w, 16);

    float di  = g_dinv[w];
    float di2 = di * di;
    float4 hs = hp4[w * 16 + sub];
    float4 bv = ((const float4*)bias)[sub];
    float4 r;
    r.x = fmaf(hs.x, di2, acc.x) + bv.x;
    r.y = fmaf(hs.y, di2, acc.y) + bv.y;
    r.z = fmaf(hs.z, di2, acc.z) + bv.z;
    r.w = fmaf(hs.w, di2, acc.w) + bv.w;
    if (half == 0) ((float4*)out)[w * 16 + sub] = r;
}

// ---------------------------------------------------------------------------
// Aggregation DOUT=40: warp per node; col=lane plus col=32+lane for lane<8.
// (measured-best form)
// ---------------------------------------------------------------------------
__global__ void aggregate40_kernel(const float* __restrict__ h,
                                   const float* __restrict__ bias,
                                   float* __restrict__ out,
                                   int n)
{
    int w = (blockIdx.x * blockDim.x + threadIdx.x) >> 5;
    if (w >= n) return;
    int lane = threadIdx.x & 31;

    int c0 = g_rowptr[w];
    int c1 = g_rowptr[w + 1];
    bool hi = (lane < 8);

    float a0 = 0.0f, a1 = 0.0f;
    for (int i = c0; i < c1; i++) {
        float2 pk = g_epack[i];
        int   s = __float_as_int(pk.x);
        float c = pk.y;
        const float* hr = &h[s * 40];
        a0 = fmaf(hr[lane], c, a0);
        if (hi) a1 = fmaf(hr[32 + lane], c, a1);
    }

    float di  = g_dinv[w];
    float di2 = di * di;
    const float* hs = &h[w * 40];
    out[w * 40 + lane] = fmaf(hs[lane], di2, a0) + bias[lane];
    if (hi)
        out[w * 40 + 32 + lane] = fmaf(hs[32 + lane], di2, a1) + bias[32 + lane];
}

// ---------------------------------------------------------------------------
// Launch
// ---------------------------------------------------------------------------
extern "C" void kernel_launch(void* const* d_in, const int* in_sizes, int n_in,
                              void* d_out, int out_size)
{
    const float* x  = (const float*)d_in[0];
    const void*  ei = d_in[1];
    const float* W1 = (const float*)d_in[2];
    const float* b1 = (const float*)d_in[3];
    const float* W2 = (const float*)d_in[4];
    const float* b2 = (const float*)d_in[5];
    const float* W3 = (const float*)d_in[6];
    const float* b3 = (const float*)d_in[7];
    float* out = (float*)d_out;

    const int N = in_sizes[0] / 128;   // 100000
    const int E = in_sizes[1] / 2;     // 1600000

    float *h, *aggA, *aggB;
    cudaGetSymbolAddress((void**)&h,    g_h);
    cudaGetSymbolAddress((void**)&aggA, g_aggA);
    cudaGetSymbolAddress((void**)&aggB, g_aggB);

    // --- prep ---
    detect_zero_kernel<<<(N + 255) / 256, 256>>>((const int*)ei, N);
    hist_kernel<<<(E + 255) / 256, 256>>>(ei, E);
    const int nb = (N + SCAN_BS - 1) / SCAN_BS;
    scan1_kernel<<<nb, SCAN_BS>>>(N);
    scan3_kernel<<<(N + 255) / 256, 256>>>(N, E);
    place_kernel<<<(E + 255) / 256, 256>>>(E);

    constexpr int TRB = 128;                       // big-GEMM row tile
    const int g2_grid  = (N + TRB - 1) / TRB;
    const int agg_grid = (N * 32 + 255) / 256;

    // --- layer 1: 128 -> 64 ---
    const int smem1 = (128 * 64 + TRB * (128 + 4)) * (int)sizeof(float);  // ~100.4KB
    cudaFuncSetAttribute(gemm64_kernel<128, TRB, false>,
                         cudaFuncAttributeMaxDynamicSharedMemorySize, smem1);
    gemm64_kernel<128, TRB, false><<<g2_grid, 128, smem1>>>(x, W1, h, N);
    aggregate64_kernel<<<agg_grid, 256>>>(h, b1, aggA, N);

    // --- layer 2: 64 -> 64 ---
    const int smem2 = (64 * 64 + TRB * (64 + 4)) * (int)sizeof(float);    // ~51.2KB
    cudaFuncSetAttribute(gemm64_kernel<64, TRB, true>,
                         cudaFuncAttributeMaxDynamicSharedMemorySize, smem2);
    gemm64_kernel<64, TRB, true><<<g2_grid, 128, smem2>>>(aggA, W2, h, N);
    aggregate64_kernel<<<agg_grid, 256>>>(h, b2, aggB, N);

    // --- layer 3: 64 -> 40 ---
    constexpr int TR3 = 64;
    const int g3_grid = (N + TR3 - 1) / TR3;
    const int smem3 = (64 * 40 + TR3 * (64 + 1)) * (int)sizeof(float);
    gemm_kernel<64, 40, 5, TR3, true><<<g3_grid, TR3 * 5, smem3>>>(aggB, W3, h, N);
    aggregate40_kernel<<<agg_grid, 256>>>(h, b3, out, N);
}